// round 2
// baseline (speedup 1.0000x reference)
#include <cuda_runtime.h>
#include <math_constants.h>

// Problem constants
#define AA 68                 // total action dim (3+3+4+25+25+8)
#define ROWS_PER_BLOCK 128
#define THREADS 128
#define ROW_PAD 69            // odd stride -> conflict-free per-thread smem row reads
#define MAX_BLOCKS 65536

__device__ float g_partials[MAX_BLOCKS];

__global__ void kl_main_kernel(const float* __restrict__ cur,
                               const float* __restrict__ prev,
                               int W)
{
    __shared__ float tile[ROWS_PER_BLOCK * ROW_PAD];
    __shared__ float xs[AA];
    __shared__ float warp_sums[THREADS / 32];

    const int tid  = threadIdx.x;
    const int row0 = blockIdx.x * ROWS_PER_BLOCK;

    const int   seg_off[7] = {0, 3, 6, 10, 35, 60, AA};
    const float inv_n[6]   = {1.f/3.f, 1.f/3.f, 0.25f, 0.04f, 0.04f, 0.125f};

    // --- segmented log_softmax of current_action (tiny; 6 threads, 1 segment each)
    if (tid < 6) {
        const int s = seg_off[tid], e = seg_off[tid + 1];
        float m = -CUDART_INF_F;
        for (int i = s; i < e; i++) m = fmaxf(m, cur[i]);
        float S = 0.f;
        for (int i = s; i < e; i++) S += __expf(cur[i] - m);
        const float lse = m + __logf(S);
        for (int i = s; i < e; i++) xs[i] = cur[i] - lse;
    }

    // --- stage tile: coalesced float4 global loads, scalar smem stores (padded rows)
    const int rows_here = min(ROWS_PER_BLOCK, W - row0);
    const float4* gsrc = reinterpret_cast<const float4*>(prev + (size_t)row0 * AA);
    if (rows_here == ROWS_PER_BLOCK) {
        // full-tile fast path: fixed trip count, no bounds checks
        const int nv4 = ROWS_PER_BLOCK * (AA / 4);         // 2176 float4
        #pragma unroll 4
        for (int i = tid; i < nv4; i += THREADS) {
            float4 v = gsrc[i];
            const int r = i / (AA / 4);
            const int c = (i % (AA / 4)) * 4;
            float* dst = &tile[r * ROW_PAD + c];
            dst[0] = v.x; dst[1] = v.y; dst[2] = v.z; dst[3] = v.w;
        }
    } else if (rows_here > 0) {
        const int nv4 = rows_here * (AA / 4);
        for (int i = tid; i < nv4; i += THREADS) {
            float4 v = gsrc[i];
            const int r = i / (AA / 4);
            const int c = (i % (AA / 4)) * 4;
            float* dst = &tile[r * ROW_PAD + c];
            dst[0] = v.x; dst[1] = v.y; dst[2] = v.z; dst[3] = v.w;
        }
    }
    __syncthreads();

    // --- per-thread row reduction (2 passes per segment, all from smem/registers)
    float acc = 0.f;
    if (tid < rows_here) {
        const float* row = &tile[tid * ROW_PAD];
        #pragma unroll
        for (int j = 0; j < 6; j++) {
            const int s = seg_off[j], e = seg_off[j + 1];
            float m = -CUDART_INF_F;
            for (int i = s; i < e; i++) m = fmaxf(m, row[i]);
            float S = 0.f, T = 0.f, U = 0.f;
            for (int i = s; i < e; i++) {
                const float z  = row[i] - m;
                const float ez = __expf(z);
                S += ez;
                T = fmaf(ez, z, T);
                U = fmaf(ez, xs[i], U);
            }
            // sum_i p_i*(t_i - x_i) = (T - U)/S - log S   with t = z - m - logS
            acc += inv_n[j] * ((T - U) * (1.f / S) - __logf(S));
        }
    }

    // --- block reduction -> one deterministic partial per block
    #pragma unroll
    for (int o = 16; o; o >>= 1) acc += __shfl_xor_sync(0xffffffffu, acc, o);
    if ((tid & 31) == 0) warp_sums[tid >> 5] = acc;
    __syncthreads();
    if (tid == 0) {
        float s = 0.f;
        #pragma unroll
        for (int w = 0; w < THREADS / 32; w++) s += warp_sums[w];
        g_partials[blockIdx.x] = s;
    }
}

__global__ void kl_finalize_kernel(float* __restrict__ out, int nblocks, float inv_w)
{
    __shared__ float warp_sums[8];
    const int tid = threadIdx.x;
    float s = 0.f;
    for (int i = tid; i < nblocks; i += 256) s += g_partials[i];
    #pragma unroll
    for (int o = 16; o; o >>= 1) s += __shfl_xor_sync(0xffffffffu, s, o);
    if ((tid & 31) == 0) warp_sums[tid >> 5] = s;
    __syncthreads();
    if (tid == 0) {
        float t = 0.f;
        #pragma unroll
        for (int w = 0; w < 8; w++) t += warp_sums[w];
        out[0] = t * inv_w;
    }
}

extern "C" void kernel_launch(void* const* d_in, const int* in_sizes, int n_in,
                              void* d_out, int out_size)
{
    const float* cur  = (const float*)d_in[0];   // [68]
    const float* prev = (const float*)d_in[1];   // [W, 68]
    float* out = (float*)d_out;

    const int W  = in_sizes[1] / AA;
    int nb = (W + ROWS_PER_BLOCK - 1) / ROWS_PER_BLOCK;
    if (nb > MAX_BLOCKS) nb = MAX_BLOCKS;        // W=524288 -> 4096 blocks

    kl_main_kernel<<<nb, THREADS>>>(cur, prev, W);
    kl_finalize_kernel<<<1, 256>>>(out, nb, 1.0f / (float)W);
}